// round 17
// baseline (speedup 1.0000x reference)
#include <cuda_runtime.h>
#include <cuda_bf16.h>
#include <cstdint>

// Plane2Depth: out[b,0,H,W] = 1 / max( s*(p*u + q*v + r), 0.1 )
// [p,q,r,s] = Wmat @ feat[b,:,H/4,W/4];  norm cancels algebraically.
//
// R16 = converged design: R7 skeleton (best measured: ncu 9.47us) +
// individually-validated micro-deltas only:
//  - W in __constant__ memory (graph-capturable D2D cudaMemcpyToSymbolAsync
//    in kernel_launch): no W LDGs in the CTA critical head.
//  - exit: tid0-only fence/commit/drain, NO trailing __syncthreads
//    (thread 0 pins the CTA; smem freed at full-CTA exit — R10/R13-safe).
//  - u-symmetry: pu2=-pu1, pu3=-pu0.

#define IN_H   192
#define IN_W   192
#define BATCH  16
#define OUT_HW 768          // 192*4
#define PLANE  (IN_H * IN_W)
#define TILE_BYTES (4 * OUT_HW * 4)   // 12288

__constant__ float4 cW[4];   // W rows

__global__ __launch_bounds__(IN_W)
void plane2depth_kernel(const float* __restrict__ feat,
                        float* __restrict__ out)
{
    __shared__ __align__(16) float sm[4][OUT_HW];   // 12288 B

    const int w = threadIdx.x;      // input column (0..191)
    const int h = blockIdx.x;       // input row
    const int b = blockIdx.y;       // batch

    // ---- load 4 channels of this pixel (each warp-coalesced 128B) ----
    const float* fp = feat + (size_t)b * 4 * PLANE + (size_t)h * IN_W + w;
    float f0 = fp[0];
    float f1 = fp[PLANE];
    float f2 = fp[2 * PLANE];
    float f3 = fp[3 * PLANE];

    // ---- W from constant cache (broadcast, no LDG) ----
    float4 m0 = cW[0];
    float4 m1 = cW[1];
    float4 m2 = cW[2];
    float4 m3 = cW[3];

    float p = fmaf(m0.x, f0, fmaf(m0.y, f1, fmaf(m0.z, f2, m0.w * f3)));
    float q = fmaf(m1.x, f0, fmaf(m1.y, f1, fmaf(m1.z, f2, m1.w * f3)));
    float r = fmaf(m2.x, f0, fmaf(m2.y, f1, fmaf(m2.z, f2, m2.w * f3)));
    float s = fmaf(m3.x, f0, fmaf(m3.y, f1, fmaf(m3.z, f2, m3.w * f3)));

    // fold s:  d = sp*u + sq*v + sr
    float sp = s * p, sq = s * q, sr = s * r;

    const float DMIN = 0.1f;   // 1.0 / MAX_DEPTH
    float pu0 = sp * -0.375f;
    float pu1 = sp * -0.125f;
    float pu2 = -pu1;          // u symmetry
    float pu3 = -pu0;

    float* smr = &sm[0][4 * w];
#pragma unroll
    for (int j = 0; j < 4; j++) {            // output sub-row (v index)
        float vj   = (float)j * 0.25f - 0.375f;
        float base = fmaf(sq, vj, sr);
        float4 o;
        float d;
        d = pu0 + base; d = fmaxf(d, DMIN); o.x = __fdividef(1.0f, d);
        d = pu1 + base; d = fmaxf(d, DMIN); o.y = __fdividef(1.0f, d);
        d = pu2 + base; d = fmaxf(d, DMIN); o.z = __fdividef(1.0f, d);
        d = pu3 + base; d = fmaxf(d, DMIN); o.w = __fdividef(1.0f, d);
        *(float4*)(smr + (size_t)j * OUT_HW) = o;   // STS.128, conflict-free
    }

    __syncthreads();   // all STS complete before the bulk engine reads SMEM

    // One 12KB bulk copy: SMEM -> GMEM rows [4h, 4h+4). Only thread 0
    // waits; the other warps retire immediately. SMEM stays allocated
    // until the whole CTA (thread 0) exits, keeping the bulk read safe.
    if (threadIdx.x == 0) {
        float* dst = out + ((size_t)b * OUT_HW + (size_t)(4 * h)) * OUT_HW;
        uint32_t saddr;
        asm volatile("{ .reg .u64 t; cvta.to.shared.u64 t, %1; cvt.u32.u64 %0, t; }"
                     : "=r"(saddr) : "l"(&sm[0][0]));
        asm volatile("fence.proxy.async.shared::cta;" ::: "memory");
        asm volatile("cp.async.bulk.global.shared::cta.bulk_group [%0], [%1], %2;"
                     :: "l"(dst), "r"(saddr), "r"((int)TILE_BYTES) : "memory");
        asm volatile("cp.async.bulk.commit_group;" ::: "memory");
        asm volatile("cp.async.bulk.wait_group 0;" ::: "memory");
    }
}

extern "C" void kernel_launch(void* const* d_in, const int* in_sizes, int n_in,
                              void* d_out, int out_size)
{
    const float* feat = (const float*)d_in[0];   // (16,4,192,192) f32
    const float* Wsrc = (const float*)d_in[1];   // (4,4) f32
    float* out = (float*)d_out;                  // (16,1,768,768) f32

    // Graph-capturable D2D copy of W into constant memory (64 bytes).
    cudaMemcpyToSymbolAsync(cW, Wsrc, 16 * sizeof(float), 0,
                            cudaMemcpyDeviceToDevice, 0);

    dim3 grid(IN_H, BATCH);      // 192 x 16 = 3072 blocks
    dim3 block(IN_W);            // 192 threads = one input row
    plane2depth_kernel<<<grid, block>>>(feat, out);
}